// round 16
// baseline (speedup 1.0000x reference)
#include <cuda_runtime.h>
#include <cstdint>

// ---------------- problem constants ----------------
#define NB   2
#define NC   256
#define HH   64
#define NPIX 4096           // 64*64
#define NN   4096           // attention sequence length
#define QKD  32
#define NCLS 19

// ---------------- scratch (device globals; no allocation allowed) ----------
__device__ float g_modal [NB*NCLS*NPIX];
__device__ float g_amodal[NB*NCLS*NPIX];
__device__ float g_q     [NB*QKD*NPIX];
__device__ float g_kk    [NB*QKD*NPIX];
__device__ float g_v     [(size_t)NB*NC*NPIX];
__device__ float g_comp  [(size_t)NB*NC*NPIX];
__device__ float g_outA  [(size_t)NB*NC*NPIX];
__device__ float g_outB  [(size_t)NB*NC*NPIX];
__device__ float g_outC  [(size_t)NB*NC*NPIX];
__device__ float g_P1    [(size_t)NB*NN*NN];     // E, then t = exp(E - rmax[n])
__device__ float g_P2    [(size_t)NB*NN*NN];     // u = exp(E - cmax[m])
__device__ float g_rmax  [NB*NN];
__device__ float g_rsum  [NB*NN];
__device__ float g_cmax  [NB*NN];
__device__ float g_csum  [NB*NN];
__device__ float g_y0    [NB*NC];
__device__ float g_se    [NB*NC];

__device__ __forceinline__ float f2tf32(float x) {
    uint32_t r;
    asm("cvt.rna.tf32.f32 %0, %1;" : "=r"(r) : "f"(x));
    return __uint_as_float(r);
}

__device__ __forceinline__ uint32_t smem_u32(const void* p) {
    return (uint32_t)__cvta_generic_to_shared(p);
}
__device__ __forceinline__ void cp_async_16B(uint32_t dst, const void* src) {
    asm volatile("cp.async.ca.shared.global [%0], [%1], 16;"
                 :: "r"(dst), "l"(src));
}
__device__ __forceinline__ void cp_async_8B(uint32_t dst, const void* src, int srcsize) {
    asm volatile("cp.async.ca.shared.global [%0], [%1], 8, %2;"
                 :: "r"(dst), "l"(src), "r"(srcsize));
}
__device__ __forceinline__ void cp_async_4B(uint32_t dst, const void* src, int srcsize) {
    asm volatile("cp.async.ca.shared.global [%0], [%1], 4, %2;"
                 :: "r"(dst), "l"(src), "r"(srcsize));
}
#define CP_COMMIT() asm volatile("cp.async.commit_group;" ::: "memory")
#define CP_WAIT(n)  asm volatile("cp.async.wait_group %0;" :: "n"(n) : "memory")

__device__ __forceinline__ void atomicMaxF(float* addr, float v) {
    if (v >= 0.f) atomicMax((int*)addr, __float_as_int(v));
    else          atomicMin((unsigned int*)addr, __float_as_uint(v));
}

#define MMA_TF32(acc, av, bv)                                              \
    asm volatile(                                                          \
        "mma.sync.aligned.m16n8k8.row.col.f32.tf32.tf32.f32 "              \
        "{%0,%1,%2,%3}, {%4,%5,%6,%7}, {%8,%9}, {%0,%1,%2,%3};"            \
        : "+f"((acc)[0]), "+f"((acc)[1]), "+f"((acc)[2]), "+f"((acc)[3])   \
        : "r"(__float_as_uint((av)[0])), "r"(__float_as_uint((av)[1])),    \
          "r"(__float_as_uint((av)[2])), "r"(__float_as_uint((av)[3])),    \
          "r"(__float_as_uint((bv)[0])), "r"(__float_as_uint((bv)[1])))

// ======================================================================
// Big conv (Cout=256): implicit GEMM, 3xTF32 hi/lo at fragment read,
// raw-fp32 smem, cp.async 2-stage. Tile 128(oc) x 64(px) -> grid 256
// blocks (~1.7/SM) for latency hiding across blocks.
// ======================================================================
__global__ __launch_bounds__(256, 2) void conv_mma(
    const float* __restrict__ p0, int c0, int bs0,
    const float* __restrict__ p1, int c1, int bs1,
    const float* __restrict__ p2, int c2, int bs2,
    const float* __restrict__ wt,
    const float* __restrict__ bias,
    float* __restrict__ out, int outBS, int Cout,
    const float* __restrict__ mask, int maskBS)
{
    const int Cin  = c0 + c1 + c2;
    const int Ktot = Cin * 9;
    const int b    = blockIdx.z;
    const int ocg  = blockIdx.y * 128;
    const int m0   = blockIdx.x * 64;

    const int tid  = threadIdx.x;
    const int lane = tid & 31;
    const int warp = tid >> 5;
    const int wm   = warp & 1;
    const int wn   = warp >> 1;          // 0..3, covers 4*16 = 64 px

    __shared__ __align__(16) float As[2][128][20];
    __shared__ __align__(16) float Bs[2][16][68];

    float acc[4][2][4];
    #pragma unroll
    for (int i = 0; i < 4; i++)
        #pragma unroll
        for (int j = 0; j < 2; j++)
            #pragma unroll
            for (int r = 0; r < 4; r++) acc[i][j][r] = 0.f;

    const int arow = tid >> 1;
    const int akc  = (tid & 1) * 8;
    const int bk   = tid >> 4;           // 0..15 (k)
    const int bm   = (tid & 15) * 4;     // 0..60 (px, 4 per thread)
    const int mpix = m0 + bm;
    const int py   = mpix >> 6;
    const int px   = mpix & 63;

    const float* wbase = wt + (size_t)(ocg + arow)*Ktot;

#define CONV_ISSUE(s_, k0_)                                                     \
    {                                                                           \
        uint32_t adst = smem_u32(&As[s_][arow][akc]);                           \
        const float* asrc = wbase + (k0_) + akc;                                \
        _Pragma("unroll")                                                       \
        for (int j = 0; j < 4; j++) {                                           \
            int kk_ = (k0_) + akc + j*2;                                        \
            cp_async_8B(adst + j*8, asrc + j*2, kk_ < Ktot ? 8 : 0);            \
        }                                                                       \
        int kB_ = (k0_) + bk;                                                   \
        int ic_ = kB_ / 9;                                                      \
        int t_  = kB_ - ic_*9;                                                  \
        int q3_ = t_ / 3;                                                       \
        int dy_ = q3_ - 1;                                                      \
        int dx_ = t_ - q3_*3 - 1;                                               \
        const float* src_ = p0;                                                 \
        if (ic_ < c0)              src_ = p0 + (size_t)b*bs0 + (size_t)ic_*NPIX;            \
        else if (ic_ < c0+c1)      src_ = p1 + (size_t)b*bs1 + (size_t)(ic_-c0)*NPIX;       \
        else if (ic_ < Cin)        src_ = p2 + (size_t)b*bs2 + (size_t)(ic_-c0-c1)*NPIX;    \
        int yy_ = py + dy_;                                                     \
        bool rv_ = (kB_ < Ktot) && (yy_ >= 0) && (yy_ < HH);                    \
        const float* rp_ = rv_ ? (src_ + yy_*HH + px + dx_) : wt;               \
        uint32_t bdst = smem_u32(&Bs[s_][bk][bm]);                              \
        _Pragma("unroll")                                                       \
        for (int j = 0; j < 4; j++) {                                           \
            int xx_ = px + dx_ + j;                                             \
            int ok_ = (rv_ && xx_ >= 0 && xx_ < HH) ? 4 : 0;                    \
            cp_async_4B(bdst + j*4, rp_ + j, ok_);                              \
        }                                                                       \
    }

    const int nIter = (Ktot + 15) >> 4;

    CONV_ISSUE(0, 0);
    CP_COMMIT();

    for (int it = 0; it < nIter; it++) {
        const int s = it & 1;
        if (it + 1 < nIter) {
            CONV_ISSUE(s ^ 1, (it + 1) << 4);
            CP_COMMIT();
            CP_WAIT(1);
        } else {
            CP_WAIT(0);
        }
        __syncthreads();

        #pragma unroll
        for (int kk2 = 0; kk2 < 2; kk2++) {
            const int kb = kk2*8 + (lane & 3);
            float ah[4][4], al[4][4];
            #pragma unroll
            for (int mf = 0; mf < 4; mf++) {
                int row = wm*64 + mf*16 + (lane >> 2);
                float v0 = As[s][row  ][kb];
                float v1 = As[s][row+8][kb];
                float v2 = As[s][row  ][kb+4];
                float v3 = As[s][row+8][kb+4];
                ah[mf][0] = f2tf32(v0); al[mf][0] = f2tf32(v0 - ah[mf][0]);
                ah[mf][1] = f2tf32(v1); al[mf][1] = f2tf32(v1 - ah[mf][1]);
                ah[mf][2] = f2tf32(v2); al[mf][2] = f2tf32(v2 - ah[mf][2]);
                ah[mf][3] = f2tf32(v3); al[mf][3] = f2tf32(v3 - ah[mf][3]);
            }
            float bh[2][2], bl[2][2];
            #pragma unroll
            for (int nf = 0; nf < 2; nf++) {
                int col = wn*16 + nf*8 + (lane >> 2);
                float w0 = Bs[s][kb  ][col];
                float w1 = Bs[s][kb+4][col];
                bh[nf][0] = f2tf32(w0); bl[nf][0] = f2tf32(w0 - bh[nf][0]);
                bh[nf][1] = f2tf32(w1); bl[nf][1] = f2tf32(w1 - bh[nf][1]);
            }
            #pragma unroll
            for (int mf = 0; mf < 4; mf++)
                #pragma unroll
                for (int nf = 0; nf < 2; nf++) {
                    MMA_TF32(acc[mf][nf], al[mf], bh[nf]);
                    MMA_TF32(acc[mf][nf], ah[mf], bl[nf]);
                    MMA_TF32(acc[mf][nf], ah[mf], bh[nf]);
                }
        }
        __syncthreads();
    }
#undef CONV_ISSUE

    float* ob = out + (size_t)b*outBS;
    const float* mb = mask ? (mask + (size_t)b*maskBS) : nullptr;
    #pragma unroll
    for (int mf = 0; mf < 4; mf++) {
        int r0 = ocg + wm*64 + mf*16 + (lane >> 2);
        int r1 = r0 + 8;
        #pragma unroll
        for (int nf = 0; nf < 2; nf++) {
            int col = m0 + wn*16 + nf*8 + (lane & 3)*2;
            if (r0 < Cout) {
                float v0 = acc[mf][nf][0] + bias[r0];
                float v1 = acc[mf][nf][1] + bias[r0];
                if (mb) {
                    v0 *= mb[(size_t)r0*NPIX + col];
                    v1 *= mb[(size_t)r0*NPIX + col + 1];
                }
                *(float2*)(ob + (size_t)r0*NPIX + col) = make_float2(v0, v1);
            }
            if (r1 < Cout) {
                float v0 = acc[mf][nf][2] + bias[r1];
                float v1 = acc[mf][nf][3] + bias[r1];
                if (mb) {
                    v0 *= mb[(size_t)r1*NPIX + col];
                    v1 *= mb[(size_t)r1*NPIX + col + 1];
                }
                *(float2*)(ob + (size_t)r1*NPIX + col) = make_float2(v0, v1);
            }
        }
    }
}

// ======================================================================
// Fused small convs (mp/ap/q/k), ONE launch, 32-row tiles, cp.async
// 2-stage pipeline (R14-proven, unchanged; 4B weight cp.async).
// ======================================================================
__global__ __launch_bounds__(256) void conv_mma_small(
    const float* __restrict__ x,
    const float* __restrict__ mmask, const float* __restrict__ amask,
    const float* __restrict__ w_mp, const float* __restrict__ b_mp,
    const float* __restrict__ w_ap, const float* __restrict__ b_ap,
    const float* __restrict__ w_q,  const float* __restrict__ b_q,
    const float* __restrict__ w_k,  const float* __restrict__ b_k,
    float* __restrict__ modal, float* __restrict__ amodal,
    float* __restrict__ qout,  float* __restrict__ kout)
{
    const int variant = blockIdx.y;
    const int b  = blockIdx.z;
    const int m0 = blockIdx.x * 128;

    const float *wt, *bias, *mask = nullptr, *p1 = nullptr;
    float* out;
    int Cout, c1;
    if (variant == 0)      { wt=w_mp; bias=b_mp; out=modal;  Cout=NCLS; c1=0;    mask=mmask; }
    else if (variant == 1) { wt=w_ap; bias=b_ap; out=amodal; Cout=NCLS; c1=0;    mask=amask; }
    else if (variant == 2) { wt=w_q;  bias=b_q;  out=qout;   Cout=QKD;  c1=NCLS; p1=mmask; }
    else                   { wt=w_k;  bias=b_k;  out=kout;   Cout=QKD;  c1=NCLS; p1=amask; }
    const int Cin   = NC + c1;
    const int Ktot  = Cin * 9;
    const int outBS = Cout * NPIX;

    const int tid  = threadIdx.x;
    const int lane = tid & 31;
    const int warp = tid >> 5;

    __shared__ __align__(16) float As[2][32][20];
    __shared__ __align__(16) float Bs[2][16][132];

    float acc[2][2][4];
    #pragma unroll
    for (int i = 0; i < 2; i++)
        #pragma unroll
        for (int j = 0; j < 2; j++)
            #pragma unroll
            for (int r = 0; r < 4; r++) acc[i][j][r] = 0.f;

    const int arow = tid >> 3;              // 0..31
    const int akc  = (tid & 7) * 2;         // 0..14
    const int bk   = tid >> 4;
    const int bm   = (tid & 15) * 8;
    const int mpix = m0 + bm;
    const int py   = mpix >> 6;
    const int px   = mpix & 63;

    const float* wbase = wt + (size_t)arow*Ktot;

#define SC_ISSUE(s_, k0_)                                                       \
    {                                                                           \
        uint32_t adst = smem_u32(&As[s_][arow][akc]);                           \
        int kk0_ = (k0_) + akc;                                                 \
        int ok0_ = (arow < Cout && kk0_     < Ktot) ? 4 : 0;                    \
        int ok1_ = (arow < Cout && kk0_ + 1 < Ktot) ? 4 : 0;                    \
        cp_async_4B(adst,     wbase + kk0_,     ok0_);                          \
        cp_async_4B(adst + 4, wbase + kk0_ + 1, ok1_);                          \
        int kB_ = (k0_) + bk;                                                   \
        int ic_ = kB_ / 9;                                                      \
        int t_  = kB_ - ic_*9;                                                  \
        int q3_ = t_ / 3;                                                       \
        int dy_ = q3_ - 1;                                                      \
        int dx_ = t_ - q3_*3 - 1;                                               \
        const float* src_ = x;                                                  \
        if (ic_ < NC)              src_ = x  + (size_t)b*(NC*NPIX)   + (size_t)ic_*NPIX;    \
        else if (ic_ < Cin)        src_ = p1 + (size_t)b*(NCLS*NPIX) + (size_t)(ic_-NC)*NPIX;\
        int yy_ = py + dy_;                                                     \
        bool rv_ = (kB_ < Ktot) && (yy_ >= 0) && (yy_ < HH);                    \
        const float* rp_ = rv_ ? (src_ + yy_*HH + px + dx_) : wt;               \
        uint32_t bdst = smem_u32(&Bs[s_][bk][bm]);                              \
        _Pragma("unroll")                                                       \
        for (int j = 0; j < 8; j++) {                                           \
            int xx_ = px + dx_ + j;                                             \
            int ok_ = (rv_ && xx_ >= 0 && xx_ < HH) ? 4 : 0;                    \
            cp_async_4B(bdst + j*4, rp_ + j, ok_);                              \
        }                                                                       \
    }

    const int nIter = (Ktot + 15) >> 4;

    SC_ISSUE(0, 0);
    CP_COMMIT();

    for (int it = 0; it < nIter; it++) {
        const int s = it & 1;
        if (it + 1 < nIter) {
            SC_ISSUE(s ^ 1, (it + 1) << 4);
            CP_COMMIT();
            CP_WAIT(1);
        } else {
            CP_WAIT(0);
        }
        __syncthreads();

        #pragma unroll
        for (int kk = 0; kk < 2; kk++) {
            const int kb = kk*8 + (lane & 3);
            float ah[2][4], al[2][4];
            #pragma unroll
            for (int mf = 0; mf < 2; mf++) {
                int row = mf*16 + (lane >> 2);
                float v0 = As[s][row  ][kb];
                float v1 = As[s][row+8][kb];
                float v2 = As[s][row  ][kb+4];
                float v3 = As[s][row+8][kb+4];
                ah[mf][0] = f2tf32(v0); al[mf][0] = f2tf32(v0 - ah[mf][0]);
                ah[mf][1] = f2tf32(v1); al[mf][1] = f2tf32(v1 - ah[mf][1]);
                ah[mf][2] = f2tf32(v2); al[mf][2] = f2tf32(v2 - ah[mf][2]);
                ah[mf][3] = f2tf32(v3); al[mf][3] = f2tf32(v3 - ah[mf][3]);
            }
            float bh[2][2], bl[2][2];
            #pragma unroll
            for (int nf = 0; nf < 2; nf++) {
                int col = warp*16 + nf*8 + (lane >> 2);
                float w0 = Bs[s][kb  ][col];
                float w1 = Bs[s][kb+4][col];
                bh[nf][0] = f2tf32(w0); bl[nf][0] = f2tf32(w0 - bh[nf][0]);
                bh[nf][1] = f2tf32(w1); bl[nf][1] = f2tf32(w1 - bh[nf][1]);
            }
            #pragma unroll
            for (int mf = 0; mf < 2; mf++)
                #pragma unroll
                for (int nf = 0; nf < 2; nf++) {
                    MMA_TF32(acc[mf][nf], al[mf], bh[nf]);
                    MMA_TF32(acc[mf][nf], ah[mf], bl[nf]);
                    MMA_TF32(acc[mf][nf], ah[mf], bh[nf]);
                }
        }
        __syncthreads();
    }
#undef SC_ISSUE

    float* ob = out + (size_t)b*outBS;
    const float* mb = mask ? (mask + (size_t)b*(NCLS*NPIX)) : nullptr;
    #pragma unroll
    for (int mf = 0; mf < 2; mf++) {
        int r0 = mf*16 + (lane >> 2);
        int r1 = r0 + 8;
        #pragma unroll
        for (int nf = 0; nf < 2; nf++) {
            int col = m0 + warp*16 + nf*8 + (lane & 3)*2;
            if (r0 < Cout) {
                float v0 = acc[mf][nf][0] + bias[r0];
                float v1 = acc[mf][nf][1] + bias[r0];
                if (mb) {
                    v0 *= mb[(size_t)r0*NPIX + col];
                    v1 *= mb[(size_t)r0*NPIX + col + 1];
                }
                *(float2*)(ob + (size_t)r0*NPIX + col) = make_float2(v0, v1);
            }
            if (r1 < Cout) {
                float v0 = acc[mf][nf][2] + bias[r1];
                float v1 = acc[mf][nf][3] + bias[r1];
                if (mb) {
                    v0 *= mb[(size_t)r1*NPIX + col];
                    v1 *= mb[(size_t)r1*NPIX + col + 1];
                }
                *(float2*)(ob + (size_t)r1*NPIX + col) = make_float2(v0, v1);
            }
        }
    }
}

// ======================================================================
// init stats: rsum/csum = 0, rmax/cmax = -inf (every replay)
// ======================================================================
__global__ __launch_bounds__(256) void init_stats_k(
    float* __restrict__ rsum, float* __restrict__ csum,
    float* __restrict__ rmax, float* __restrict__ cmax)
{
    int i = blockIdx.x*256 + threadIdx.x;
    if (i < NB*NN) {
        rsum[i] = 0.f; csum[i] = 0.f;
        float ninf = __int_as_float(0xff800000);
        rmax[i] = ninf; cmax[i] = ninf;
    }
}

// ======================================================================
// Fused max kernel: compute each E tile ONCE; STORE E into g_P1;
// row+col maxes via atomics.
// ======================================================================
__global__ __launch_bounds__(256) void attn_maxboth_k(
    const float* __restrict__ Q, const float* __restrict__ K,
    float* __restrict__ rmax, float* __restrict__ cmax,
    float* __restrict__ Eout)
{
    const int b  = blockIdx.z;
    const int n0 = blockIdx.y * 64;
    const int m0 = blockIdx.x * 64;
    const int tid = threadIdx.x;
    const int tx = tid & 15, ty = tid >> 4;

    __shared__ float qs[32][64];
    __shared__ float ks[32][64];
    __shared__ float redR[64][17];
    __shared__ float redC[64][17];

    const float* qb = Q + (size_t)b*QKD*NN;
    const float* kb = K + (size_t)b*QKD*NN;

    for (int i = tid; i < 32*16; i += 256) {
        int d = i >> 4, c4 = i & 15;
        *(float4*)&qs[d][c4*4] = *(const float4*)(qb + (size_t)d*NN + n0 + c4*4);
        *(float4*)&ks[d][c4*4] = *(const float4*)(kb + (size_t)d*NN + m0 + c4*4);
    }
    __syncthreads();

    float e[4][4];
    #pragma unroll
    for (int i = 0; i < 4; i++)
        #pragma unroll
        for (int j = 0; j < 4; j++) e[i][j] = 0.f;

    #pragma unroll
    for (int d = 0; d < 32; d++) {
        float4 a  = *(const float4*)&qs[d][ty*4];
        float4 bv = *(const float4*)&ks[d][tx*4];
        float aa[4] = {a.x, a.y, a.z, a.w};
        float bb[4] = {bv.x, bv.y, bv.z, bv.w};
        #pragma unroll
        for (int i = 0; i < 4; i++)
            #pragma unroll
            for (int j = 0; j < 4; j++) e[i][j] += aa[i]*bb[j];
    }

    // store E tile (consumed by attn_p_k, which overwrites it with P1)
    #pragma unroll
    for (int i = 0; i < 4; i++) {
        size_t base = (size_t)b*NN*NN + (size_t)(n0 + ty*4 + i)*NN + m0 + tx*4;
        *(float4*)(Eout + base) = make_float4(e[i][0], e[i][1], e[i][2], e[i][3]);
    }

    float rmx[4], cmx[4];
    #pragma unroll
    for (int i = 0; i < 4; i++) {
        rmx[i] = fmaxf(fmaxf(e[i][0], e[i][1]), fmaxf(e[i][2], e[i][3]));
        cmx[i] = fmaxf(fmaxf(e[0][i], e[1][i]), fmaxf(e[2][i], e[3][i]));
    }
    #pragma unroll
    for (int i = 0; i < 4; i++) {
        redR[ty*4+i][tx] = rmx[i];
        redC[tx*4+i][ty] = cmx[i];
    }
    __syncthreads();
    if (tid < 64) {
        float mr = redR[tid][0];
        float mc = redC[tid][0];
        #pragma unroll
        for (int j = 1; j < 16; j++) {
            mr = fmaxf(mr, redR[tid][j]);
            mc = fmaxf(mc, redC[tid][j]);
        }
        atomicMaxF(rmax + (size_t)b*NN + n0 + tid, mr);
        atomicMaxF(cmax + (size_t)b*NN + m0 + tid, mc);
    }
}

// ======================================================================
// P kernel: READS staged E from g_P1, computes t/u, overwrites P1 and
// writes P2; accumulates rsum / csum via block reduce + atomics.
// ======================================================================
__global__ __launch_bounds__(256) void attn_p_k(
    const float* __restrict__ rmax, const float* __restrict__ cmax,
    float* __restrict__ rsum, float* __restrict__ csum,
    float* __restrict__ P1, float* __restrict__ P2)
{
    const int b  = blockIdx.z;
    const int n0 = blockIdx.y * 64;
    const int m0 = blockIdx.x * 64;
    const int tid = threadIdx.x;
    const int tx = tid & 15, ty = tid >> 4;

    __shared__ float redR[64][17];
    __shared__ float redC[64][17];

    float rm[4], cm[4];
    #pragma unroll
    for (int i = 0; i < 4; i++) {
        rm[i] = rmax[(size_t)b*NN + n0 + ty*4 + i];
        cm[i] = cmax[(size_t)b*NN + m0 + tx*4 + i];
    }

    float rs[4] = {0.f, 0.f, 0.f, 0.f};
    float cs[4] = {0.f, 0.f, 0.f, 0.f};

    #pragma unroll
    for (int i = 0; i < 4; i++) {
        size_t base = (size_t)b*NN*NN + (size_t)(n0 + ty*4 + i)*NN + m0 + tx*4;
        float4 ev = *(const float4*)(P1 + base);
        float e[4] = {ev.x, ev.y, ev.z, ev.w};
        float4 v1, v2;
        float* pv1 = (float*)&v1;
        float* pv2 = (float*)&v2;
        #pragma unroll
        for (int j = 0; j < 4; j++) {
            float t = __expf(e[j] - rm[i]);
            float u = __expf(e[j] - cm[j]);
            pv1[j] = t;
            pv2[j] = u;
            rs[i] += t;
            cs[j] += u;
        }
        *(float4*)(P1 + base) = v1;
        *(float4*)(P2 + base) = v2;
    }

    #pragma unroll
    for (int i = 0; i < 4; i++) {
        redR[ty*4+i][tx] = rs[i];
        redC[tx*4+i][ty] = cs[i];
    }
    __syncthreads();
    if (tid < 64) {
        float sr = redR[tid][0];
        float sc = redC[tid][0];
        #pragma unroll
        for (int j = 1; j < 16; j++) { sr += redR[tid][j]; sc += redC[tid][j]; }
        atomicAdd(rsum + (size_t)b*NN + n0 + tid, sr);
        atomicAdd(csum + (size_t)b*NN + m0 + tid, sc);
    }
}

// ======================================================================
// tf32 GEMM for out_b / out_c, cp.async 2-stage pipeline (R14-proven).
// ======================================================================
__global__ __launch_bounds__(256, 2) void gemm_vp_mma(
    const float* __restrict__ V,
    const float* __restrict__ P1f, const float* __restrict__ P2f,
    const float* __restrict__ rsum, const float* __restrict__ csum,
    float* __restrict__ outBp, float* __restrict__ outCp)
{
    const int z = blockIdx.z;
    const int b = z >> 1;
    const int variant = z & 1;
    const float* __restrict__ P = variant ? P2f : P1f;
    const float* __restrict__ S = variant ? csum : rsum;
    float* __restrict__ out     = variant ? outCp : outBp;

    const int c0 = blockIdx.y * 128;
    const int m0 = blockIdx.x * 128;

    const int tid  = threadIdx.x;
    const int lane = tid & 31;
    const int warp = tid >> 5;
    const int wm   = warp & 1;
    const int wn   = warp >> 1;

    __shared__ __align__(16) float Vs[2][128][20];
    __shared__ __align__(16) float Ps[2][16][132];

    const float* Vb = V + (size_t)b*NC*NN;
    const float* Pb = P + (size_t)b*NN*NN;
    const float* Sb = S + (size_t)b*NN;

    float acc[4][4][4];
    #pragma unroll
    for (int i = 0; i < 4; i++)
        #pragma unroll
        for (int j = 0; j < 4; j++)
            #pragma unroll
            for (int r = 0; r < 4; r++) acc[i][j][r] = 0.f;

    const int arow = tid >> 1;
    const int akc  = (tid & 1) * 8;
    const int bk   = tid >> 4;
    const int bm   = (tid & 15) * 8;

    const float* vsrc  = Vb + (size_t)(c0 + arow)*NN + akc;
    const float* p1src = Pb + (size_t)(m0 + arow)*NN + akc;   // variant 0
    const float* p2src = Pb + (size_t)bk*NN + m0 + bm;        // variant 1

#define G_ISSUE(s_, k0_)                                                        \
    {                                                                           \
        uint32_t ad = smem_u32(&Vs[s_][arow][akc]);                             \
        cp_async_16B(ad,      vsrc + (k0_));                                    \
        cp_async_16B(ad + 16, vsrc + (k0_) + 4);                                \
        if (variant) {                                                          \
            uint32_t bd = smem_u32(&Ps[s_][bk][bm]);                            \
            cp_async_16B(bd,      p2src + (size_t)(k0_)*NN);                    \
            cp_async_16B(bd + 16, p2src + (size_t)(k0_)*NN + 4);                \
        }                                                                       \
    }

    float4 r0, r1;   // variant-0 B prefetch registers
    G_ISSUE(0, 0);
    CP_COMMIT();
    if (!variant) { r0 = *(const float4*)(p1src); r1 = *(const float4*)(p1src + 4); }

    for (int it = 0; it < NN/16; it++) {
        const int s  = it & 1;
        const int k0 = it << 4;
        if (it + 1 < NN/16) {
            G_ISSUE(s ^ 1, k0 + 16);
            CP_COMMIT();
            CP_WAIT(1);
        } else {
            CP_WAIT(0);
        }
        if (!variant) {
            Ps[s][akc+0][arow] = r0.x; Ps[s][akc+1][arow] = r0.y;
            Ps[s][akc+2][arow] = r0.z; Ps[s][akc+3][arow] = r0.w;
            Ps[s][akc+4][arow] = r1.x; Ps[s][akc+5][arow] = r1.y;
            Ps[s][akc+6][arow] = r1.z; Ps[s][akc+7][arow] = r1.w;
            if (it + 1 < NN/16) {
                r0 = *(const float4*)(p1src + k0 + 16);
                r1 = *(const float4*)(p1src + k0 + 20);
            }
        }
        __syncthreads();

        #pragma unroll
        for (int kk = 0; kk < 2; kk++) {
            const int kb = kk*8 + (lane & 3);
            float a[4][4];
            #pragma unroll
            for (int mf = 0; mf < 4; mf++) {
                int row = wm*64 + mf*16 + (lane >> 2);
                a[mf][0] = f2tf32(Vs[s][row  ][kb]);
                a[mf][1] = f2tf32(Vs[s][row+8][kb]);
                a[mf][2] = f2tf32(Vs[s][row  ][kb+4]);
                a[mf][3] = f2tf32(Vs[s][row+8][kb+4]);
            }
            float bf[4][2];
            #pragma unroll
            for (int nf = 0; nf < 4; nf++) {
                int col = wn*32 + nf*8 + (lane >> 2);
                bf[nf][0] = f2tf32(Ps[s][kb  ][col]);
                bf[nf][1] = f2tf32(Ps[s][kb+4][col]);
            }
            #pragma unroll
            for (int mf = 0; mf < 4; mf++)
                #pragma unroll
                for (int nf = 0; nf < 4; nf++)
                    MMA_TF32(acc[mf][nf], a[mf], bf[nf]);
        }
        __syncthreads();
    }
#undef G_ISSUE

    float inv0[4], inv1[4];
    #pragma unroll
    for (int nf = 0; nf < 4; nf++) {
        int col = m0 + wn*32 + nf*8 + (lane & 3)*2;
        inv0[nf] = 1.f / Sb[col];
        inv1[nf] = 1.f / Sb[col + 1];
    }

    float* ob = out + (size_t)b*NC*NN;
    #pragma unroll
    for (int mf = 0; mf < 4; mf++) {
        int row = c0 + wm*64 + mf*16 + (lane >> 2);
        #pragma unroll
        for (int nf = 0; nf < 4; nf++) {
            int col = m0 + wn*32 + nf*8 + (lane & 3)*2;
            *(float2*)(ob + (size_t)row*NN + col) =
                make_float2(acc[mf][nf][0]*inv0[nf], acc[mf][nf][1]*inv1[nf]);
            *(float2*)(ob + (size_t)(row+8)*NN + col) =
                make_float2(acc[mf][nf][2]*inv0[nf], acc[mf][nf][3]*inv1[nf]);
        }
    }
}

// ======================================================================
// SE layer pieces
// ======================================================================
__global__ __launch_bounds__(256) void se_reduce_k(
    const float* __restrict__ comp, float* __restrict__ y0)
{
    int b = blockIdx.y, c = blockIdx.x;
    const float* p = comp + ((size_t)b*NC + c)*NPIX;
    float s = 0.f;
    for (int i = threadIdx.x; i < NPIX; i += 256) s += p[i];
    #pragma unroll
    for (int o = 16; o; o >>= 1) s += __shfl_xor_sync(0xffffffffu, s, o);
    __shared__ float red[8];
    if ((threadIdx.x & 31) == 0) red[threadIdx.x >> 5] = s;
    __syncthreads();
    if (threadIdx.x == 0) {
        float t = 0.f;
        for (int i = 0; i < 8; i++) t += red[i];
        y0[b*NC + c] = t * (1.f / NPIX);
    }
}

__global__ __launch_bounds__(256) void se_mlp_k(
    const float* __restrict__ y0, const float* __restrict__ w1,
    const float* __restrict__ w2, float* __restrict__ se)
{
    int b = blockIdx.x, tid = threadIdx.x;
    __shared__ float ys[NC];
    __shared__ float hs[32];
    ys[tid] = y0[b*NC + tid];
    __syncthreads();
    if (tid < 32) {
        float a = 0.f;
        for (int j = 0; j < NC; j++) a += ys[j] * w1[tid*NC + j];
        hs[tid] = fmaxf(a, 0.f);
    }
    __syncthreads();
    float a = 0.f;
    #pragma unroll
    for (int j = 0; j < 32; j++) a += hs[j] * w2[tid*32 + j];
    se[b*NC + tid] = 1.f / (1.f + __expf(-a));
}

__global__ __launch_bounds__(256) void se_scale_k(
    const float* __restrict__ comp, const float* __restrict__ se,
    float* __restrict__ outA)
{
    size_t i = (size_t)blockIdx.x * 256 + threadIdx.x;
    if (i < (size_t)NB*NC*NPIX) {
        size_t bc = i >> 12;
        outA[i] = comp[i] * se[bc];
    }
}

// ======================================================================
// host launcher
// ======================================================================
template <typename T>
static float* symaddr(T& sym) {
    void* p = nullptr;
    cudaGetSymbolAddress(&p, sym);
    return (float*)p;
}

extern "C" void kernel_launch(void* const* d_in, const int* in_sizes, int n_in,
                              void* d_out, int out_size)
{
    const float* x      = (const float*)d_in[0];
    const float* mmask  = (const float*)d_in[1];
    const float* amask  = (const float*)d_in[2];
    const float* w_mp   = (const float*)d_in[3];
    const float* b_mp   = (const float*)d_in[4];
    const float* w_ap   = (const float*)d_in[5];
    const float* b_ap   = (const float*)d_in[6];
    const float* w_q    = (const float*)d_in[7];
    const float* b_q    = (const float*)d_in[8];
    const float* w_k    = (const float*)d_in[9];
    const float* b_k    = (const float*)d_in[10];
    const float* w_v    = (const float*)d_in[11];
    const float* b_v    = (const float*)d_in[12];
    const float* w_comp = (const float*)d_in[13];
    const float* b_comp = (const float*)d_in[14];
    const float* w_out  = (const float*)d_in[15];
    const float* b_out  = (const float*)d_in[16];
    const float* w_se1  = (const float*)d_in[17];
    const float* w_se2  = (const float*)d_in[18];
    float* out = (float*)d_out;

    float* modal  = symaddr(g_modal);
    float* amodal = symaddr(g_amodal);
    float* q      = symaddr(g_q);
    float* k      = symaddr(g_kk);
    float* v      = symaddr(g_v);
    float* comp   = symaddr(g_comp);
    float* outA   = symaddr(g_outA);
    float* outB   = symaddr(g_outB);
    float* outC   = symaddr(g_outC);
    float* P1     = symaddr(g_P1);
    float* P2     = symaddr(g_P2);
    float* rmax   = symaddr(g_rmax);
    float* rsum   = symaddr(g_rsum);
    float* cmax   = symaddr(g_cmax);
    float* csum   = symaddr(g_csum);
    float* y0     = symaddr(g_y0);
    float* se     = symaddr(g_se);

    const int BSX = NC*NPIX;
    const int BSM = NCLS*NPIX;

    const dim3 gBig(NPIX/64, 2, NB);      // 64-px tiles -> 256 blocks

    // ---- init stats accumulators (sums=0, maxes=-inf) ----
    init_stats_k<<<(NB*NN + 255)/256, 256>>>(rsum, csum, rmax, cmax);

    // ---- all four small convs (mp/ap/q/k) in one launch, pipelined ----
    conv_mma_small<<<dim3(NPIX/128, 4, NB), 256>>>(
        x, mmask, amask, w_mp, b_mp, w_ap, b_ap, w_q, b_q, w_k, b_k,
        modal, amodal, q, k);

    // ---- v conv ----
    conv_mma<<<gBig, 256>>>(x, NC, BSX, nullptr,0,0, nullptr,0,0,
        w_v, b_v, v, BSX, NC, nullptr, 0);

    // ---- comp conv over concat(x, modal_x, amodal_x) ----
    conv_mma<<<gBig, 256>>>(x, NC, BSX, modal, NCLS, BSM, amodal, NCLS, BSM,
        w_comp, b_comp, comp, BSX, NC, nullptr, 0);

    // ---- SE layer -> out_a ----
    se_reduce_k<<<dim3(NC, NB), 256>>>(comp, y0);
    se_mlp_k<<<NB, 256>>>(y0, w_se1, w_se2, se);
    se_scale_k<<<(NB*NC*NPIX)/256, 256>>>(comp, se, outA);

    // ---- fused row+col max over E; E staged into g_P1 ----
    attn_maxboth_k<<<dim3(NN/64, NN/64, NB), 256>>>(q, k, rmax, cmax, P1);

    // ---- exp matrices from staged E + sum accumulation ----
    attn_p_k<<<dim3(NN/64, NN/64, NB), 256>>>(rmax, cmax, rsum, csum, P1, P2);

    // ---- out_b / out_c (pipelined tf32 GEMM, normalization in epilogue) ----
    gemm_vp_mma<<<dim3(NN/128, NC/128, NB*2), 256>>>(v, P1, P2, rsum, csum, outB, outC);

    // ---- final conv over concat(out_a, out_b, out_c) ----
    conv_mma<<<gBig, 256>>>(outA, NC, BSX, outB, NC, BSX, outC, NC, BSX,
        w_out, b_out, out, BSX, NC, nullptr, 0);
}

// round 17
// speedup vs baseline: 1.0920x; 1.0920x over previous
#include <cuda_runtime.h>
#include <cstdint>

// ---------------- problem constants ----------------
#define NB   2
#define NC   256
#define HH   64
#define NPIX 4096           // 64*64
#define NN   4096           // attention sequence length
#define QKD  32
#define NCLS 19

// ---------------- scratch (device globals; no allocation allowed) ----------
__device__ float g_modal [NB*NCLS*NPIX];
__device__ float g_amodal[NB*NCLS*NPIX];
__device__ float g_q     [NB*QKD*NPIX];
__device__ float g_kk    [NB*QKD*NPIX];
__device__ float g_v     [(size_t)NB*NC*NPIX];
__device__ float g_comp  [(size_t)NB*NC*NPIX];
__device__ float g_outA  [(size_t)NB*NC*NPIX];
__device__ float g_outB  [(size_t)NB*NC*NPIX];
__device__ float g_outC  [(size_t)NB*NC*NPIX];
__device__ float g_P1    [(size_t)NB*NN*NN];     // E, then t = exp(E - rmax[n])
__device__ float g_P2    [(size_t)NB*NN*NN];     // u = exp(E - cmax[m])
__device__ float g_rmax  [NB*NN];
__device__ float g_rsum  [NB*NN];
__device__ float g_cmax  [NB*NN];
__device__ float g_csum  [NB*NN];
__device__ float g_y0    [NB*NC];
__device__ float g_se    [NB*NC];

__device__ __forceinline__ float f2tf32(float x) {
    uint32_t r;
    asm("cvt.rna.tf32.f32 %0, %1;" : "=r"(r) : "f"(x));
    return __uint_as_float(r);
}

__device__ __forceinline__ uint32_t smem_u32(const void* p) {
    return (uint32_t)__cvta_generic_to_shared(p);
}
__device__ __forceinline__ void cp_async_16B(uint32_t dst, const void* src) {
    asm volatile("cp.async.ca.shared.global [%0], [%1], 16;"
                 :: "r"(dst), "l"(src));
}
__device__ __forceinline__ void cp_async_8B(uint32_t dst, const void* src, int srcsize) {
    asm volatile("cp.async.ca.shared.global [%0], [%1], 8, %2;"
                 :: "r"(dst), "l"(src), "r"(srcsize));
}
__device__ __forceinline__ void cp_async_4B(uint32_t dst, const void* src, int srcsize) {
    asm volatile("cp.async.ca.shared.global [%0], [%1], 4, %2;"
                 :: "r"(dst), "l"(src), "r"(srcsize));
}
#define CP_COMMIT() asm volatile("cp.async.commit_group;" ::: "memory")
#define CP_WAIT(n)  asm volatile("cp.async.wait_group %0;" :: "n"(n) : "memory")

__device__ __forceinline__ void atomicMaxF(float* addr, float v) {
    if (v >= 0.f) atomicMax((int*)addr, __float_as_int(v));
    else          atomicMin((unsigned int*)addr, __float_as_uint(v));
}

#define MMA_TF32(acc, av, bv)                                              \
    asm volatile(                                                          \
        "mma.sync.aligned.m16n8k8.row.col.f32.tf32.tf32.f32 "              \
        "{%0,%1,%2,%3}, {%4,%5,%6,%7}, {%8,%9}, {%0,%1,%2,%3};"            \
        : "+f"((acc)[0]), "+f"((acc)[1]), "+f"((acc)[2]), "+f"((acc)[3])   \
        : "r"(__float_as_uint((av)[0])), "r"(__float_as_uint((av)[1])),    \
          "r"(__float_as_uint((av)[2])), "r"(__float_as_uint((av)[3])),    \
          "r"(__float_as_uint((bv)[0])), "r"(__float_as_uint((bv)[1])))

// ======================================================================
// Shared big-conv body: implicit GEMM, 3xTF32 hi/lo at fragment read,
// raw-fp32 smem, cp.async 2-stage. Tile 128(oc) x 128(px), BK=16.
// (Exact R14 structure — the proven-fastest variant.)
// ======================================================================
struct ConvSmem {
    __align__(16) float As[2][128][20];
    __align__(16) float Bs[2][16][132];
};

__device__ __forceinline__ void conv_body(
    ConvSmem* sm,
    const float* __restrict__ p0, int c0, int bs0,
    const float* __restrict__ p1, int c1, int bs1,
    const float* __restrict__ p2, int c2, int bs2,
    const float* __restrict__ wt,
    const float* __restrict__ bias,
    float* __restrict__ out, int outBS, int Cout,
    const float* __restrict__ mask, int maskBS,
    int b, int ocg, int m0)
{
    const int Cin  = c0 + c1 + c2;
    const int Ktot = Cin * 9;

    const int tid  = threadIdx.x;
    const int lane = tid & 31;
    const int warp = tid >> 5;
    const int wm   = warp & 1;
    const int wn   = warp >> 1;

    auto& As = sm->As;
    auto& Bs = sm->Bs;

    float acc[4][4][4];
    #pragma unroll
    for (int i = 0; i < 4; i++)
        #pragma unroll
        for (int j = 0; j < 4; j++)
            #pragma unroll
            for (int r = 0; r < 4; r++) acc[i][j][r] = 0.f;

    const int arow = tid >> 1;
    const int akc  = (tid & 1) * 8;
    const int bk   = tid >> 4;
    const int bm   = (tid & 15) * 8;
    const int mpix = m0 + bm;
    const int py   = mpix >> 6;
    const int px   = mpix & 63;

    const float* wbase = wt + (size_t)(ocg + arow)*Ktot;

#define CONV_ISSUE(s_, k0_)                                                     \
    {                                                                           \
        uint32_t adst = smem_u32(&As[s_][arow][akc]);                           \
        const float* asrc = wbase + (k0_) + akc;                                \
        _Pragma("unroll")                                                       \
        for (int j = 0; j < 4; j++) {                                           \
            int kk_ = (k0_) + akc + j*2;                                        \
            cp_async_8B(adst + j*8, asrc + j*2, kk_ < Ktot ? 8 : 0);            \
        }                                                                       \
        int kB_ = (k0_) + bk;                                                   \
        int ic_ = kB_ / 9;                                                      \
        int t_  = kB_ - ic_*9;                                                  \
        int q3_ = t_ / 3;                                                       \
        int dy_ = q3_ - 1;                                                      \
        int dx_ = t_ - q3_*3 - 1;                                               \
        const float* src_ = p0;                                                 \
        if (ic_ < c0)              src_ = p0 + (size_t)b*bs0 + (size_t)ic_*NPIX;            \
        else if (ic_ < c0+c1)      src_ = p1 + (size_t)b*bs1 + (size_t)(ic_-c0)*NPIX;       \
        else if (ic_ < Cin)        src_ = p2 + (size_t)b*bs2 + (size_t)(ic_-c0-c1)*NPIX;    \
        int yy_ = py + dy_;                                                     \
        bool rv_ = (kB_ < Ktot) && (yy_ >= 0) && (yy_ < HH);                    \
        const float* rp_ = rv_ ? (src_ + yy_*HH + px + dx_) : wt;               \
        uint32_t bdst = smem_u32(&Bs[s_][bk][bm]);                              \
        _Pragma("unroll")                                                       \
        for (int j = 0; j < 8; j++) {                                           \
            int xx_ = px + dx_ + j;                                             \
            int ok_ = (rv_ && xx_ >= 0 && xx_ < HH) ? 4 : 0;                    \
            cp_async_4B(bdst + j*4, rp_ + j, ok_);                              \
        }                                                                       \
    }

    const int nIter = (Ktot + 15) >> 4;

    CONV_ISSUE(0, 0);
    CP_COMMIT();

    for (int it = 0; it < nIter; it++) {
        const int s = it & 1;
        if (it + 1 < nIter) {
            CONV_ISSUE(s ^ 1, (it + 1) << 4);
            CP_COMMIT();
            CP_WAIT(1);
        } else {
            CP_WAIT(0);
        }
        __syncthreads();

        #pragma unroll
        for (int kk2 = 0; kk2 < 2; kk2++) {
            const int kb = kk2*8 + (lane & 3);
            float ah[4][4], al[4][4];
            #pragma unroll
            for (int mf = 0; mf < 4; mf++) {
                int row = wm*64 + mf*16 + (lane >> 2);
                float v0 = As[s][row  ][kb];
                float v1 = As[s][row+8][kb];
                float v2 = As[s][row  ][kb+4];
                float v3 = As[s][row+8][kb+4];
                ah[mf][0] = f2tf32(v0); al[mf][0] = f2tf32(v0 - ah[mf][0]);
                ah[mf][1] = f2tf32(v1); al[mf][1] = f2tf32(v1 - ah[mf][1]);
                ah[mf][2] = f2tf32(v2); al[mf][2] = f2tf32(v2 - ah[mf][2]);
                ah[mf][3] = f2tf32(v3); al[mf][3] = f2tf32(v3 - ah[mf][3]);
            }
            float bh[4][2], bl[4][2];
            #pragma unroll
            for (int nf = 0; nf < 4; nf++) {
                int col = wn*32 + nf*8 + (lane >> 2);
                float w0 = Bs[s][kb  ][col];
                float w1 = Bs[s][kb+4][col];
                bh[nf][0] = f2tf32(w0); bl[nf][0] = f2tf32(w0 - bh[nf][0]);
                bh[nf][1] = f2tf32(w1); bl[nf][1] = f2tf32(w1 - bh[nf][1]);
            }
            #pragma unroll
            for (int mf = 0; mf < 4; mf++)
                #pragma unroll
                for (int nf = 0; nf < 4; nf++) {
                    MMA_TF32(acc[mf][nf], al[mf], bh[nf]);
                    MMA_TF32(acc[mf][nf], ah[mf], bl[nf]);
                    MMA_TF32(acc[mf][nf], ah[mf], bh[nf]);
                }
        }
        __syncthreads();
    }
#undef CONV_ISSUE

    float* ob = out + (size_t)b*outBS;
    const float* mb = mask ? (mask + (size_t)b*maskBS) : nullptr;
    #pragma unroll
    for (int mf = 0; mf < 4; mf++) {
        int r0 = ocg + wm*64 + mf*16 + (lane >> 2);
        int r1 = r0 + 8;
        #pragma unroll
        for (int nf = 0; nf < 4; nf++) {
            int col = m0 + wn*32 + nf*8 + (lane & 3)*2;
            if (r0 < Cout) {
                float v0 = acc[mf][nf][0] + bias[r0];
                float v1 = acc[mf][nf][1] + bias[r0];
                if (mb) {
                    v0 *= mb[(size_t)r0*NPIX + col];
                    v1 *= mb[(size_t)r0*NPIX + col + 1];
                }
                *(float2*)(ob + (size_t)r0*NPIX + col) = make_float2(v0, v1);
            }
            if (r1 < Cout) {
                float v0 = acc[mf][nf][2] + bias[r1];
                float v1 = acc[mf][nf][3] + bias[r1];
                if (mb) {
                    v0 *= mb[(size_t)r1*NPIX + col];
                    v1 *= mb[(size_t)r1*NPIX + col + 1];
                }
                *(float2*)(ob + (size_t)r1*NPIX + col) = make_float2(v0, v1);
            }
        }
    }
}

// ---- standalone big conv (used for the final out conv) ----
__global__ __launch_bounds__(256, 2) void conv_mma(
    const float* __restrict__ p0, int c0, int bs0,
    const float* __restrict__ p1, int c1, int bs1,
    const float* __restrict__ p2, int c2, int bs2,
    const float* __restrict__ wt,
    const float* __restrict__ bias,
    float* __restrict__ out, int outBS, int Cout,
    const float* __restrict__ mask, int maskBS)
{
    __shared__ ConvSmem sm;
    conv_body(&sm, p0, c0, bs0, p1, c1, bs1, p2, c2, bs2,
              wt, bias, out, outBS, Cout, mask, maskBS,
              blockIdx.z, blockIdx.y * 128, blockIdx.x * 128);
}

// ---- fused v + comp convs: 256 blocks in ONE launch ----
__global__ __launch_bounds__(256, 2) void conv_mma_vc(
    const float* __restrict__ x,
    const float* __restrict__ modal, const float* __restrict__ amodal,
    const float* __restrict__ w_v,    const float* __restrict__ b_v,
    const float* __restrict__ w_comp, const float* __restrict__ b_comp,
    float* __restrict__ vout, float* __restrict__ compout)
{
    __shared__ ConvSmem sm;
    const int variant = blockIdx.y >> 1;         // 0: v conv, 1: comp conv
    const int ocg     = (blockIdx.y & 1) * 128;
    const int BSX = NC*NPIX;
    const int BSM = NCLS*NPIX;
    if (variant == 0) {
        conv_body(&sm, x, NC, BSX, nullptr,0,0, nullptr,0,0,
                  w_v, b_v, vout, BSX, NC, nullptr, 0,
                  blockIdx.z, ocg, blockIdx.x * 128);
    } else {
        conv_body(&sm, x, NC, BSX, modal, NCLS, BSM, amodal, NCLS, BSM,
                  w_comp, b_comp, compout, BSX, NC, nullptr, 0,
                  blockIdx.z, ocg, blockIdx.x * 128);
    }
}

// ======================================================================
// Fused small convs (mp/ap/q/k), ONE launch, 32-row tiles, cp.async
// 2-stage pipeline (R14-proven, unchanged; 4B weight cp.async).
// ======================================================================
__global__ __launch_bounds__(256) void conv_mma_small(
    const float* __restrict__ x,
    const float* __restrict__ mmask, const float* __restrict__ amask,
    const float* __restrict__ w_mp, const float* __restrict__ b_mp,
    const float* __restrict__ w_ap, const float* __restrict__ b_ap,
    const float* __restrict__ w_q,  const float* __restrict__ b_q,
    const float* __restrict__ w_k,  const float* __restrict__ b_k,
    float* __restrict__ modal, float* __restrict__ amodal,
    float* __restrict__ qout,  float* __restrict__ kout)
{
    const int variant = blockIdx.y;
    const int b  = blockIdx.z;
    const int m0 = blockIdx.x * 128;

    const float *wt, *bias, *mask = nullptr, *p1 = nullptr;
    float* out;
    int Cout, c1;
    if (variant == 0)      { wt=w_mp; bias=b_mp; out=modal;  Cout=NCLS; c1=0;    mask=mmask; }
    else if (variant == 1) { wt=w_ap; bias=b_ap; out=amodal; Cout=NCLS; c1=0;    mask=amask; }
    else if (variant == 2) { wt=w_q;  bias=b_q;  out=qout;   Cout=QKD;  c1=NCLS; p1=mmask; }
    else                   { wt=w_k;  bias=b_k;  out=kout;   Cout=QKD;  c1=NCLS; p1=amask; }
    const int Cin   = NC + c1;
    const int Ktot  = Cin * 9;
    const int outBS = Cout * NPIX;

    const int tid  = threadIdx.x;
    const int lane = tid & 31;
    const int warp = tid >> 5;

    __shared__ __align__(16) float As[2][32][20];
    __shared__ __align__(16) float Bs[2][16][132];

    float acc[2][2][4];
    #pragma unroll
    for (int i = 0; i < 2; i++)
        #pragma unroll
        for (int j = 0; j < 2; j++)
            #pragma unroll
            for (int r = 0; r < 4; r++) acc[i][j][r] = 0.f;

    const int arow = tid >> 3;              // 0..31
    const int akc  = (tid & 7) * 2;         // 0..14
    const int bk   = tid >> 4;
    const int bm   = (tid & 15) * 8;
    const int mpix = m0 + bm;
    const int py   = mpix >> 6;
    const int px   = mpix & 63;

    const float* wbase = wt + (size_t)arow*Ktot;

#define SC_ISSUE(s_, k0_)                                                       \
    {                                                                           \
        uint32_t adst = smem_u32(&As[s_][arow][akc]);                           \
        int kk0_ = (k0_) + akc;                                                 \
        int ok0_ = (arow < Cout && kk0_     < Ktot) ? 4 : 0;                    \
        int ok1_ = (arow < Cout && kk0_ + 1 < Ktot) ? 4 : 0;                    \
        cp_async_4B(adst,     wbase + kk0_,     ok0_);                          \
        cp_async_4B(adst + 4, wbase + kk0_ + 1, ok1_);                          \
        int kB_ = (k0_) + bk;                                                   \
        int ic_ = kB_ / 9;                                                      \
        int t_  = kB_ - ic_*9;                                                  \
        int q3_ = t_ / 3;                                                       \
        int dy_ = q3_ - 1;                                                      \
        int dx_ = t_ - q3_*3 - 1;                                               \
        const float* src_ = x;                                                  \
        if (ic_ < NC)              src_ = x  + (size_t)b*(NC*NPIX)   + (size_t)ic_*NPIX;    \
        else if (ic_ < Cin)        src_ = p1 + (size_t)b*(NCLS*NPIX) + (size_t)(ic_-NC)*NPIX;\
        int yy_ = py + dy_;                                                     \
        bool rv_ = (kB_ < Ktot) && (yy_ >= 0) && (yy_ < HH);                    \
        const float* rp_ = rv_ ? (src_ + yy_*HH + px + dx_) : wt;               \
        uint32_t bdst = smem_u32(&Bs[s_][bk][bm]);                              \
        _Pragma("unroll")                                                       \
        for (int j = 0; j < 8; j++) {                                           \
            int xx_ = px + dx_ + j;                                             \
            int ok_ = (rv_ && xx_ >= 0 && xx_ < HH) ? 4 : 0;                    \
            cp_async_4B(bdst + j*4, rp_ + j, ok_);                              \
        }                                                                       \
    }

    const int nIter = (Ktot + 15) >> 4;

    SC_ISSUE(0, 0);
    CP_COMMIT();

    for (int it = 0; it < nIter; it++) {
        const int s = it & 1;
        if (it + 1 < nIter) {
            SC_ISSUE(s ^ 1, (it + 1) << 4);
            CP_COMMIT();
            CP_WAIT(1);
        } else {
            CP_WAIT(0);
        }
        __syncthreads();

        #pragma unroll
        for (int kk = 0; kk < 2; kk++) {
            const int kb = kk*8 + (lane & 3);
            float ah[2][4], al[2][4];
            #pragma unroll
            for (int mf = 0; mf < 2; mf++) {
                int row = mf*16 + (lane >> 2);
                float v0 = As[s][row  ][kb];
                float v1 = As[s][row+8][kb];
                float v2 = As[s][row  ][kb+4];
                float v3 = As[s][row+8][kb+4];
                ah[mf][0] = f2tf32(v0); al[mf][0] = f2tf32(v0 - ah[mf][0]);
                ah[mf][1] = f2tf32(v1); al[mf][1] = f2tf32(v1 - ah[mf][1]);
                ah[mf][2] = f2tf32(v2); al[mf][2] = f2tf32(v2 - ah[mf][2]);
                ah[mf][3] = f2tf32(v3); al[mf][3] = f2tf32(v3 - ah[mf][3]);
            }
            float bh[2][2], bl[2][2];
            #pragma unroll
            for (int nf = 0; nf < 2; nf++) {
                int col = warp*16 + nf*8 + (lane >> 2);
                float w0 = Bs[s][kb  ][col];
                float w1 = Bs[s][kb+4][col];
                bh[nf][0] = f2tf32(w0); bl[nf][0] = f2tf32(w0 - bh[nf][0]);
                bh[nf][1] = f2tf32(w1); bl[nf][1] = f2tf32(w1 - bh[nf][1]);
            }
            #pragma unroll
            for (int mf = 0; mf < 2; mf++)
                #pragma unroll
                for (int nf = 0; nf < 2; nf++) {
                    MMA_TF32(acc[mf][nf], al[mf], bh[nf]);
                    MMA_TF32(acc[mf][nf], ah[mf], bl[nf]);
                    MMA_TF32(acc[mf][nf], ah[mf], bh[nf]);
                }
        }
        __syncthreads();
    }
#undef SC_ISSUE

    float* ob = out + (size_t)b*outBS;
    const float* mb = mask ? (mask + (size_t)b*(NCLS*NPIX)) : nullptr;
    #pragma unroll
    for (int mf = 0; mf < 2; mf++) {
        int r0 = mf*16 + (lane >> 2);
        int r1 = r0 + 8;
        #pragma unroll
        for (int nf = 0; nf < 2; nf++) {
            int col = m0 + warp*16 + nf*8 + (lane & 3)*2;
            if (r0 < Cout) {
                float v0 = acc[mf][nf][0] + bias[r0];
                float v1 = acc[mf][nf][1] + bias[r0];
                if (mb) {
                    v0 *= mb[(size_t)r0*NPIX + col];
                    v1 *= mb[(size_t)r0*NPIX + col + 1];
                }
                *(float2*)(ob + (size_t)r0*NPIX + col) = make_float2(v0, v1);
            }
            if (r1 < Cout) {
                float v0 = acc[mf][nf][2] + bias[r1];
                float v1 = acc[mf][nf][3] + bias[r1];
                if (mb) {
                    v0 *= mb[(size_t)r1*NPIX + col];
                    v1 *= mb[(size_t)r1*NPIX + col + 1];
                }
                *(float2*)(ob + (size_t)r1*NPIX + col) = make_float2(v0, v1);
            }
        }
    }
}

// ======================================================================
// init stats: rsum/csum = 0, rmax/cmax = -inf (every replay)
// ======================================================================
__global__ __launch_bounds__(256) void init_stats_k(
    float* __restrict__ rsum, float* __restrict__ csum,
    float* __restrict__ rmax, float* __restrict__ cmax)
{
    int i = blockIdx.x*256 + threadIdx.x;
    if (i < NB*NN) {
        rsum[i] = 0.f; csum[i] = 0.f;
        float ninf = __int_as_float(0xff800000);
        rmax[i] = ninf; cmax[i] = ninf;
    }
}

// ======================================================================
// Fused max kernel: compute each E tile ONCE; STORE E into g_P1;
// row+col maxes via atomics.
// ======================================================================
__global__ __launch_bounds__(256) void attn_maxboth_k(
    const float* __restrict__ Q, const float* __restrict__ K,
    float* __restrict__ rmax, float* __restrict__ cmax,
    float* __restrict__ Eout)
{
    const int b  = blockIdx.z;
    const int n0 = blockIdx.y * 64;
    const int m0 = blockIdx.x * 64;
    const int tid = threadIdx.x;
    const int tx = tid & 15, ty = tid >> 4;

    __shared__ float qs[32][64];
    __shared__ float ks[32][64];
    __shared__ float redR[64][17];
    __shared__ float redC[64][17];

    const float* qb = Q + (size_t)b*QKD*NN;
    const float* kb = K + (size_t)b*QKD*NN;

    for (int i = tid; i < 32*16; i += 256) {
        int d = i >> 4, c4 = i & 15;
        *(float4*)&qs[d][c4*4] = *(const float4*)(qb + (size_t)d*NN + n0 + c4*4);
        *(float4*)&ks[d][c4*4] = *(const float4*)(kb + (size_t)d*NN + m0 + c4*4);
    }
    __syncthreads();

    float e[4][4];
    #pragma unroll
    for (int i = 0; i < 4; i++)
        #pragma unroll
        for (int j = 0; j < 4; j++) e[i][j] = 0.f;

    #pragma unroll
    for (int d = 0; d < 32; d++) {
        float4 a  = *(const float4*)&qs[d][ty*4];
        float4 bv = *(const float4*)&ks[d][tx*4];
        float aa[4] = {a.x, a.y, a.z, a.w};
        float bb[4] = {bv.x, bv.y, bv.z, bv.w};
        #pragma unroll
        for (int i = 0; i < 4; i++)
            #pragma unroll
            for (int j = 0; j < 4; j++) e[i][j] += aa[i]*bb[j];
    }

    // store E tile (consumed by attn_p_k, which overwrites it with P1)
    #pragma unroll
    for (int i = 0; i < 4; i++) {
        size_t base = (size_t)b*NN*NN + (size_t)(n0 + ty*4 + i)*NN + m0 + tx*4;
        *(float4*)(Eout + base) = make_float4(e[i][0], e[i][1], e[i][2], e[i][3]);
    }

    float rmx[4], cmx[4];
    #pragma unroll
    for (int i = 0; i < 4; i++) {
        rmx[i] = fmaxf(fmaxf(e[i][0], e[i][1]), fmaxf(e[i][2], e[i][3]));
        cmx[i] = fmaxf(fmaxf(e[0][i], e[1][i]), fmaxf(e[2][i], e[3][i]));
    }
    #pragma unroll
    for (int i = 0; i < 4; i++) {
        redR[ty*4+i][tx] = rmx[i];
        redC[tx*4+i][ty] = cmx[i];
    }
    __syncthreads();
    if (tid < 64) {
        float mr = redR[tid][0];
        float mc = redC[tid][0];
        #pragma unroll
        for (int j = 1; j < 16; j++) {
            mr = fmaxf(mr, redR[tid][j]);
            mc = fmaxf(mc, redC[tid][j]);
        }
        atomicMaxF(rmax + (size_t)b*NN + n0 + tid, mr);
        atomicMaxF(cmax + (size_t)b*NN + m0 + tid, mc);
    }
}

// ======================================================================
// P kernel: READS staged E from g_P1, computes t/u, overwrites P1 and
// writes P2; accumulates rsum / csum via block reduce + atomics.
// ======================================================================
__global__ __launch_bounds__(256) void attn_p_k(
    const float* __restrict__ rmax, const float* __restrict__ cmax,
    float* __restrict__ rsum, float* __restrict__ csum,
    float* __restrict__ P1, float* __restrict__ P2)
{
    const int b  = blockIdx.z;
    const int n0 = blockIdx.y * 64;
    const int m0 = blockIdx.x * 64;
    const int tid = threadIdx.x;
    const int tx = tid & 15, ty = tid >> 4;

    __shared__ float redR[64][17];
    __shared__ float redC[64][17];

    float rm[4], cm[4];
    #pragma unroll
    for (int i = 0; i < 4; i++) {
        rm[i] = rmax[(size_t)b*NN + n0 + ty*4 + i];
        cm[i] = cmax[(size_t)b*NN + m0 + tx*4 + i];
    }

    float rs[4] = {0.f, 0.f, 0.f, 0.f};
    float cs[4] = {0.f, 0.f, 0.f, 0.f};

    #pragma unroll
    for (int i = 0; i < 4; i++) {
        size_t base = (size_t)b*NN*NN + (size_t)(n0 + ty*4 + i)*NN + m0 + tx*4;
        float4 ev = *(const float4*)(P1 + base);
        float e[4] = {ev.x, ev.y, ev.z, ev.w};
        float4 v1, v2;
        float* pv1 = (float*)&v1;
        float* pv2 = (float*)&v2;
        #pragma unroll
        for (int j = 0; j < 4; j++) {
            float t = __expf(e[j] - rm[i]);
            float u = __expf(e[j] - cm[j]);
            pv1[j] = t;
            pv2[j] = u;
            rs[i] += t;
            cs[j] += u;
        }
        *(float4*)(P1 + base) = v1;
        *(float4*)(P2 + base) = v2;
    }

    #pragma unroll
    for (int i = 0; i < 4; i++) {
        redR[ty*4+i][tx] = rs[i];
        redC[tx*4+i][ty] = cs[i];
    }
    __syncthreads();
    if (tid < 64) {
        float sr = redR[tid][0];
        float sc = redC[tid][0];
        #pragma unroll
        for (int j = 1; j < 16; j++) { sr += redR[tid][j]; sc += redC[tid][j]; }
        atomicAdd(rsum + (size_t)b*NN + n0 + tid, sr);
        atomicAdd(csum + (size_t)b*NN + m0 + tid, sc);
    }
}

// ======================================================================
// tf32 GEMM for out_b / out_c, cp.async 2-stage pipeline (R14-proven).
// ======================================================================
__global__ __launch_bounds__(256, 2) void gemm_vp_mma(
    const float* __restrict__ V,
    const float* __restrict__ P1f, const float* __restrict__ P2f,
    const float* __restrict__ rsum, const float* __restrict__ csum,
    float* __restrict__ outBp, float* __restrict__ outCp)
{
    const int z = blockIdx.z;
    const int b = z >> 1;
    const int variant = z & 1;
    const float* __restrict__ P = variant ? P2f : P1f;
    const float* __restrict__ S = variant ? csum : rsum;
    float* __restrict__ out     = variant ? outCp : outBp;

    const int c0 = blockIdx.y * 128;
    const int m0 = blockIdx.x * 128;

    const int tid  = threadIdx.x;
    const int lane = tid & 31;
    const int warp = tid >> 5;
    const int wm   = warp & 1;
    const int wn   = warp >> 1;

    __shared__ __align__(16) float Vs[2][128][20];
    __shared__ __align__(16) float Ps[2][16][132];

    const float* Vb = V + (size_t)b*NC*NN;
    const float* Pb = P + (size_t)b*NN*NN;
    const float* Sb = S + (size_t)b*NN;

    float acc[4][4][4];
    #pragma unroll
    for (int i = 0; i < 4; i++)
        #pragma unroll
        for (int j = 0; j < 4; j++)
            #pragma unroll
            for (int r = 0; r < 4; r++) acc[i][j][r] = 0.f;

    const int arow = tid >> 1;
    const int akc  = (tid & 1) * 8;
    const int bk   = tid >> 4;
    const int bm   = (tid & 15) * 8;

    const float* vsrc  = Vb + (size_t)(c0 + arow)*NN + akc;
    const float* p1src = Pb + (size_t)(m0 + arow)*NN + akc;   // variant 0
    const float* p2src = Pb + (size_t)bk*NN + m0 + bm;        // variant 1

#define G_ISSUE(s_, k0_)                                                        \
    {                                                                           \
        uint32_t ad = smem_u32(&Vs[s_][arow][akc]);                             \
        cp_async_16B(ad,      vsrc + (k0_));                                    \
        cp_async_16B(ad + 16, vsrc + (k0_) + 4);                                \
        if (variant) {                                                          \
            uint32_t bd = smem_u32(&Ps[s_][bk][bm]);                            \
            cp_async_16B(bd,      p2src + (size_t)(k0_)*NN);                    \
            cp_async_16B(bd + 16, p2src + (size_t)(k0_)*NN + 4);                \
        }                                                                       \
    }

    float4 r0, r1;   // variant-0 B prefetch registers
    G_ISSUE(0, 0);
    CP_COMMIT();
    if (!variant) { r0 = *(const float4*)(p1src); r1 = *(const float4*)(p1src + 4); }

    for (int it = 0; it < NN/16; it++) {
        const int s  = it & 1;
        const int k0 = it << 4;
        if (it + 1 < NN/16) {
            G_ISSUE(s ^ 1, k0 + 16);
            CP_COMMIT();
            CP_WAIT(1);
        } else {
            CP_WAIT(0);
        }
        if (!variant) {
            Ps[s][akc+0][arow] = r0.x; Ps[s][akc+1][arow] = r0.y;
            Ps[s][akc+2][arow] = r0.z; Ps[s][akc+3][arow] = r0.w;
            Ps[s][akc+4][arow] = r1.x; Ps[s][akc+5][arow] = r1.y;
            Ps[s][akc+6][arow] = r1.z; Ps[s][akc+7][arow] = r1.w;
            if (it + 1 < NN/16) {
                r0 = *(const float4*)(p1src + k0 + 16);
                r1 = *(const float4*)(p1src + k0 + 20);
            }
        }
        __syncthreads();

        #pragma unroll
        for (int kk = 0; kk < 2; kk++) {
            const int kb = kk*8 + (lane & 3);
            float a[4][4];
            #pragma unroll
            for (int mf = 0; mf < 4; mf++) {
                int row = wm*64 + mf*16 + (lane >> 2);
                a[mf][0] = f2tf32(Vs[s][row  ][kb]);
                a[mf][1] = f2tf32(Vs[s][row+8][kb]);
                a[mf][2] = f2tf32(Vs[s][row  ][kb+4]);
                a[mf][3] = f2tf32(Vs[s][row+8][kb+4]);
            }
            float bf[4][2];
            #pragma unroll
            for (int nf = 0; nf < 4; nf++) {
                int col = wn*32 + nf*8 + (lane >> 2);
                bf[nf][0] = f2tf32(Ps[s][kb  ][col]);
                bf[nf][1] = f2tf32(Ps[s][kb+4][col]);
            }
            #pragma unroll
            for (int mf = 0; mf < 4; mf++)
                #pragma unroll
                for (int nf = 0; nf < 4; nf++)
                    MMA_TF32(acc[mf][nf], a[mf], bf[nf]);
        }
        __syncthreads();
    }
#undef G_ISSUE

    float inv0[4], inv1[4];
    #pragma unroll
    for (int nf = 0; nf < 4; nf++) {
        int col = m0 + wn*32 + nf*8 + (lane & 3)*2;
        inv0[nf] = 1.f / Sb[col];
        inv1[nf] = 1.f / Sb[col + 1];
    }

    float* ob = out + (size_t)b*NC*NN;
    #pragma unroll
    for (int mf = 0; mf < 4; mf++) {
        int row = c0 + wm*64 + mf*16 + (lane >> 2);
        #pragma unroll
        for (int nf = 0; nf < 4; nf++) {
            int col = m0 + wn*32 + nf*8 + (lane & 3)*2;
            *(float2*)(ob + (size_t)row*NN + col) =
                make_float2(acc[mf][nf][0]*inv0[nf], acc[mf][nf][1]*inv1[nf]);
            *(float2*)(ob + (size_t)(row+8)*NN + col) =
                make_float2(acc[mf][nf][2]*inv0[nf], acc[mf][nf][3]*inv1[nf]);
        }
    }
}

// ======================================================================
// SE layer pieces
// ======================================================================
__global__ __launch_bounds__(256) void se_reduce_k(
    const float* __restrict__ comp, float* __restrict__ y0)
{
    int b = blockIdx.y, c = blockIdx.x;
    const float* p = comp + ((size_t)b*NC + c)*NPIX;
    float s = 0.f;
    for (int i = threadIdx.x; i < NPIX; i += 256) s += p[i];
    #pragma unroll
    for (int o = 16; o; o >>= 1) s += __shfl_xor_sync(0xffffffffu, s, o);
    __shared__ float red[8];
    if ((threadIdx.x & 31) == 0) red[threadIdx.x >> 5] = s;
    __syncthreads();
    if (threadIdx.x == 0) {
        float t = 0.f;
        for (int i = 0; i < 8; i++) t += red[i];
        y0[b*NC + c] = t * (1.f / NPIX);
    }
}

__global__ __launch_bounds__(256) void se_mlp_k(
    const float* __restrict__ y0, const float* __restrict__ w1,
    const float* __restrict__ w2, float* __restrict__ se)
{
    int b = blockIdx.x, tid = threadIdx.x;
    __shared__ float ys[NC];
    __shared__ float hs[32];
    ys[tid] = y0[b*NC + tid];
    __syncthreads();
    if (tid < 32) {
        float a = 0.f;
        for (int j = 0; j < NC; j++) a += ys[j] * w1[tid*NC + j];
        hs[tid] = fmaxf(a, 0.f);
    }
    __syncthreads();
    float a = 0.f;
    #pragma unroll
    for (int j = 0; j < 32; j++) a += hs[j] * w2[tid*32 + j];
    se[b*NC + tid] = 1.f / (1.f + __expf(-a));
}

__global__ __launch_bounds__(256) void se_scale_k(
    const float* __restrict__ comp, const float* __restrict__ se,
    float* __restrict__ outA)
{
    size_t i = (size_t)blockIdx.x * 256 + threadIdx.x;
    if (i < (size_t)NB*NC*NPIX) {
        size_t bc = i >> 12;
        outA[i] = comp[i] * se[bc];
    }
}

// ======================================================================
// host launcher
// ======================================================================
template <typename T>
static float* symaddr(T& sym) {
    void* p = nullptr;
    cudaGetSymbolAddress(&p, sym);
    return (float*)p;
}

extern "C" void kernel_launch(void* const* d_in, const int* in_sizes, int n_in,
                              void* d_out, int out_size)
{
    const float* x      = (const float*)d_in[0];
    const float* mmask  = (const float*)d_in[1];
    const float* amask  = (const float*)d_in[2];
    const float* w_mp   = (const float*)d_in[3];
    const float* b_mp   = (const float*)d_in[4];
    const float* w_ap   = (const float*)d_in[5];
    const float* b_ap   = (const float*)d_in[6];
    const float* w_q    = (const float*)d_in[7];
    const float* b_q    = (const float*)d_in[8];
    const float* w_k    = (const float*)d_in[9];
    const float* b_k    = (const float*)d_in[10];
    const float* w_v    = (const float*)d_in[11];
    const float* b_v    = (const float*)d_in[12];
    const float* w_comp = (const float*)d_in[13];
    const float* b_comp = (const float*)d_in[14];
    const float* w_out  = (const float*)d_in[15];
    const float* b_out  = (const float*)d_in[16];
    const float* w_se1  = (const float*)d_in[17];
    const float* w_se2  = (const float*)d_in[18];
    float* out = (float*)d_out;

    float* modal  = symaddr(g_modal);
    float* amodal = symaddr(g_amodal);
    float* q      = symaddr(g_q);
    float* k      = symaddr(g_kk);
    float* v      = symaddr(g_v);
    float* comp   = symaddr(g_comp);
    float* outA   = symaddr(g_outA);
    float* outB   = symaddr(g_outB);
    float* outC   = symaddr(g_outC);
    float* P1     = symaddr(g_P1);
    float* P2     = symaddr(g_P2);
    float* rmax   = symaddr(g_rmax);
    float* rsum   = symaddr(g_rsum);
    float* cmax   = symaddr(g_cmax);
    float* csum   = symaddr(g_csum);
    float* y0     = symaddr(g_y0);
    float* se     = symaddr(g_se);

    const int BSX = NC*NPIX;

    // ---- init stats accumulators (sums=0, maxes=-inf) ----
    init_stats_k<<<(NB*NN + 255)/256, 256>>>(rsum, csum, rmax, cmax);

    // ---- all four small convs (mp/ap/q/k) in one launch, pipelined ----
    conv_mma_small<<<dim3(NPIX/128, 4, NB), 256>>>(
        x, mmask, amask, w_mp, b_mp, w_ap, b_ap, w_q, b_q, w_k, b_k,
        modal, amodal, q, k);

    // ---- v conv + comp conv fused into ONE launch (256 blocks) ----
    conv_mma_vc<<<dim3(NPIX/128, 4, NB), 256>>>(
        x, modal, amodal, w_v, b_v, w_comp, b_comp, v, comp);

    // ---- SE layer -> out_a ----
    se_reduce_k<<<dim3(NC, NB), 256>>>(comp, y0);
    se_mlp_k<<<NB, 256>>>(y0, w_se1, w_se2, se);
    se_scale_k<<<(NB*NC*NPIX)/256, 256>>>(comp, se, outA);

    // ---- fused row+col max over E; E staged into g_P1 ----
    attn_maxboth_k<<<dim3(NN/64, NN/64, NB), 256>>>(q, k, rmax, cmax, P1);

    // ---- exp matrices from staged E + sum accumulation ----
    attn_p_k<<<dim3(NN/64, NN/64, NB), 256>>>(rmax, cmax, rsum, csum, P1, P2);

    // ---- out_b / out_c (pipelined tf32 GEMM, normalization in epilogue) ----
    gemm_vp_mma<<<dim3(NN/128, NC/128, NB*2), 256>>>(v, P1, P2, rsum, csum, outB, outC);

    // ---- final conv over concat(out_a, out_b, out_c) ----
    conv_mma<<<dim3(NPIX/128, 2, NB), 256>>>(outA, NC, BSX, outB, NC, BSX, outC, NC, BSX,
        w_out, b_out, out, BSX, NC, nullptr, 0);
}